// round 9
// baseline (speedup 1.0000x reference)
#include <cuda_runtime.h>
#include <cstdint>

#define BB 64
#define SS 512
#define HH 768
#define LL 9
#define NROWS (BB*SS)
#define NCH 16          // chunks per batch
#define CHL 32          // steps per chunk

static __device__ float g_emis[NROWS * LL];     // natural-log emissions
static __device__ float g_mats[BB * NCH * 84];  // 9x9 linear matrices + scale

#define LOG2E 1.4426950408889634f
#define LN2   0.6931471805599453f

// ---------------------------------------------------------------------------
// Fused kernel: emissions GEMM (register-prefetch pipelined) + per-chunk
// 9x9 transition products. 256 threads, 256 rows/block, 128 blocks.
// Block bx covers batch b = bx/2, timesteps t in [(bx&1)*256, +256),
// i.e. global chunks (bx&1)*8 + w for warps w = 0..7.
// (unchanged from the 76.4us passing version)
// ---------------------------------------------------------------------------
#define EB 256
#define ROWS_PB 256
#define HCH 32
#define NHC (HH / HCH)        // 24 chunks of h
#define XSTR 36               // floats per staged row (32 used + pad, 16B-aligned)
#define OFF_X 0
#define SM_XBUF (ROWS_PB * XSTR)          // 9216 floats
#define OFF_WC SM_XBUF                    // 9216
#define OFF_EM (OFF_WC + LL * HH)         // 9216 + 6912 = 16128
#define EMSTR 10
#define OFF_MK (OFF_EM + ROWS_PB * EMSTR) // 16128 + 2560 = 18688
#define SM_FLOATS (OFF_MK + ROWS_PB)      // 18944 floats
#define FUSED_SMEM (SM_FLOATS * 4)        // 75776 bytes

extern __shared__ float sm[];

__device__ __forceinline__ void rescale3(float& a0, float& a1, float& a2, float& sc)
{
    float mx = fmaxf(fmaxf(a0, a1), a2);
#pragma unroll
    for (int o = 16; o > 0; o >>= 1)
        mx = fmaxf(mx, __shfl_xor_sync(0xFFFFFFFFu, mx, o));
    int ex = (__float_as_int(mx) >> 23) - 127;
    float s = __int_as_float((127 - ex) << 23);
    a0 *= s; a1 *= s; a2 *= s;
    sc += (float)ex;
}

__global__ __launch_bounds__(EB) void fused_kernel(
    const float* __restrict__ hid,
    const float* __restrict__ W,
    const float* __restrict__ bias,
    const int*   __restrict__ mask,
    const float* __restrict__ trans,
    float* __restrict__ out)
{
    const int tid = threadIdx.x;
    const int bx  = blockIdx.x;
    const int r0  = bx * ROWS_PB;
    float* Xs = sm + OFF_X;           // [256][36]
    float* Wc = sm + OFF_WC;          // [9][768]
    float* Em = sm + OFF_EM;          // [256][10]
    int*   Mk = (int*)(sm + OFF_MK);  // [256]

    // each thread's 8 staging slots (row r, h4 group w4), fixed across chunks
    int s_r[8], s_w4[8];
#pragma unroll
    for (int o = 0; o < 8; o++) {
        int f = tid + o * EB;          // 0..2047
        s_r[o] = f >> 3; s_w4[o] = f & 7;
    }

    // ---- stage W (transposed to [j][h]), mask; zero out scalar ----
    for (int idx = tid; idx < HH * LL; idx += EB) {
        int h = idx / LL, j = idx - h * LL;
        Wc[j * HH + h] = W[idx];
    }
    Mk[tid] = mask[r0 + tid];   // row index == b*SS + t
    if (bx == 0 && tid == 0) out[0] = 0.0f;

    float acc[LL];
#pragma unroll
    for (int j = 0; j < LL; j++) acc[j] = bias[j];

    // ---- prologue: load chunk 0 into registers, store to smem ----
    float4 pf[8];
#pragma unroll
    for (int o = 0; o < 8; o++)
        pf[o] = *reinterpret_cast<const float4*>(
            hid + (size_t)(r0 + s_r[o]) * HH + 0 + 4 * s_w4[o]);
#pragma unroll
    for (int o = 0; o < 8; o++)
        *reinterpret_cast<float4*>(Xs + s_r[o] * XSTR + 4 * s_w4[o]) = pf[o];
    __syncthreads();   // chunk 0 staged (also covers Wc / Mk)

    for (int c = 0; c < NHC; c++) {
        // prefetch next chunk into registers (LDG latency hidden by compute)
        if (c + 1 < NHC) {
            const int hc = (c + 1) * HCH;
#pragma unroll
            for (int o = 0; o < 8; o++)
                pf[o] = *reinterpret_cast<const float4*>(
                    hid + (size_t)(r0 + s_r[o]) * HH + hc + 4 * s_w4[o]);
        }

        // compute on chunk c from smem
        const int hc = c * HCH;
        const float* xp = Xs + tid * XSTR;
#pragma unroll
        for (int h4 = 0; h4 < 8; h4++) {
            float4 x = *reinterpret_cast<const float4*>(xp + 4 * h4);
#pragma unroll
            for (int j = 0; j < LL; j++) {
                float4 w = *reinterpret_cast<const float4*>(Wc + j * HH + hc + 4 * h4);
                acc[j] = fmaf(x.x, w.x, fmaf(x.y, w.y,
                         fmaf(x.z, w.z, fmaf(x.w, w.w, acc[j]))));
            }
        }

        if (c + 1 < NHC) {
            __syncthreads();   // all done reading chunk c
#pragma unroll
            for (int o = 0; o < 8; o++)
                *reinterpret_cast<float4*>(Xs + s_r[o] * XSTR + 4 * s_w4[o]) = pf[o];
            __syncthreads();   // chunk c+1 staged
        }
    }

    // ---- store emissions: global (for combine) + smem (for chunk phase) ----
    {
        float* ep = g_emis + (size_t)(r0 + tid) * LL;
#pragma unroll
        for (int j = 0; j < LL; j++) { ep[j] = acc[j]; Em[tid * EMSTR + j] = acc[j]; }
    }
    __syncthreads();

    // ---- chunk phase: warp w computes chunk product for its 32 steps ----
    const int wid  = tid >> 5;
    const int lane = tid & 31;
    const int b    = bx >> 1;
    const int gc   = (bx & 1) * 8 + wid;          // global chunk 0..15

    const int l  = (lane < 27) ? lane : 26;
    const int i  = l / 3;
    const int jb = 3 * (l - 3 * i);

    float ET0[LL], ET1[LL], ET2[LL];
#pragma unroll
    for (int k = 0; k < LL; k++) {
        ET0[k] = __expf(trans[k * LL + jb + 0]);
        ET1[k] = __expf(trans[k * LL + jb + 1]);
        ET2[k] = __expf(trans[k * LL + jb + 2]);
    }

    float a0 = (i == jb + 0) ? 1.0f : 0.0f;
    float a1 = (i == jb + 1) ? 1.0f : 0.0f;
    float a2 = (i == jb + 2) ? 1.0f : 0.0f;
    float sc = 0.0f;

    const int lt0 = wid * CHL;                 // block-local step base
    const int ts  = (gc == 0) ? 1 : 0;         // skip t=0 globally

    float e0 = Em[(lt0 + ts) * EMSTR + jb];
    float e1 = Em[(lt0 + ts) * EMSTR + jb + 1];
    float e2 = Em[(lt0 + ts) * EMSTR + jb + 2];
    int mk = Mk[lt0 + ts];
    int cnt = 0;

    for (int t = ts; t < CHL; t++) {
        float f0 = __expf(e0), f1 = __expf(e1), f2 = __expf(e2);
        int m = mk;
        if (t + 1 < CHL) {
            e0 = Em[(lt0 + t + 1) * EMSTR + jb];
            e1 = Em[(lt0 + t + 1) * EMSTR + jb + 1];
            e2 = Em[(lt0 + t + 1) * EMSTR + jb + 2];
            mk = Mk[lt0 + t + 1];
        }
        float r0s = __shfl_sync(0xFFFFFFFFu, a0, 3*i    );
        float r1s = __shfl_sync(0xFFFFFFFFu, a1, 3*i    );
        float r2s = __shfl_sync(0xFFFFFFFFu, a2, 3*i    );
        float r3s = __shfl_sync(0xFFFFFFFFu, a0, 3*i + 1);
        float r4s = __shfl_sync(0xFFFFFFFFu, a1, 3*i + 1);
        float r5s = __shfl_sync(0xFFFFFFFFu, a2, 3*i + 1);
        float r6s = __shfl_sync(0xFFFFFFFFu, a0, 3*i + 2);
        float r7s = __shfl_sync(0xFFFFFFFFu, a1, 3*i + 2);
        float r8s = __shfl_sync(0xFFFFFFFFu, a2, 3*i + 2);

        float n0 = r0s*ET0[0] + r1s*ET0[1]; n0 += r2s*ET0[2] + r3s*ET0[3];
        n0 += r4s*ET0[4] + r5s*ET0[5];      n0 += r6s*ET0[6] + r7s*ET0[7] + r8s*ET0[8];
        float n1 = r0s*ET1[0] + r1s*ET1[1]; n1 += r2s*ET1[2] + r3s*ET1[3];
        n1 += r4s*ET1[4] + r5s*ET1[5];      n1 += r6s*ET1[6] + r7s*ET1[7] + r8s*ET1[8];
        float n2 = r0s*ET2[0] + r1s*ET2[1]; n2 += r2s*ET2[2] + r3s*ET2[3];
        n2 += r4s*ET2[4] + r5s*ET2[5];      n2 += r6s*ET2[6] + r7s*ET2[7] + r8s*ET2[8];
        n0 *= f0; n1 *= f1; n2 *= f2;

        a0 = m ? n0 : a0;  a1 = m ? n1 : a1;  a2 = m ? n2 : a2;
        if (((++cnt) & 7) == 0) rescale3(a0, a1, a2, sc);
    }

    rescale3(a0, a1, a2, sc);

    float* mb = g_mats + (size_t)(b * NCH + gc) * 84;
    if (lane < 27) {
        mb[i * LL + jb + 0] = a0;
        mb[i * LL + jb + 1] = a1;
        mb[i * LL + jb + 2] = a2;
    }
    if (lane == 0) mb[81] = sc;
}

// ---------------------------------------------------------------------------
// Kernel 2: per-batch fold (warp 0) + numerator (warp 1). Same 64-thread
// shape as the passing version; only change: the 16 chunk matrices are
// staged into smem with parallel coalesced loads first, so the fold loop
// reads smem instead of doing 16 dependent global round-trips.
// ---------------------------------------------------------------------------
__global__ __launch_bounds__(64) void combine_kernel(
    const int*   __restrict__ mask,
    const int*   __restrict__ labels,
    const float* __restrict__ start_trans,
    const float* __restrict__ end_trans,
    const float* __restrict__ trans,
    float* __restrict__ out)
{
    __shared__ float Ms[NCH * 84];
    __shared__ float sh_denom, sh_num;
    const int b = blockIdx.x;
    const int tid = threadIdx.x;
    const int wid = tid >> 5;
    const int lane = tid & 31;

    // parallel coalesced staging of all 16 chunk matrices (21 loads/thread)
    const float* gsrc = g_mats + (size_t)b * NCH * 84;
    for (int idx = tid; idx < NCH * 84; idx += 64) Ms[idx] = gsrc[idx];
    __syncthreads();

    if (wid == 0) {
        const int j = (lane < LL) ? lane : (LL - 1);
        const float* em = g_emis + (size_t)b * SS * LL;

        float a = start_trans[j] + em[j];
        float mx = a;
#pragma unroll
        for (int o = 16; o > 0; o >>= 1)
            mx = fmaxf(mx, __shfl_xor_sync(0xFFFFFFFFu, mx, o));
        float v  = __expf(a - mx);
        float sc = mx * LOG2E;

        for (int c = 0; c < NCH; c++) {
            const float* mb = Ms + c * 84;
            float col[LL];
#pragma unroll
            for (int i2 = 0; i2 < LL; i2++) col[i2] = mb[i2 * LL + j];
            float msc = mb[81];

            float n = 0.0f;
#pragma unroll
            for (int i2 = 0; i2 < LL; i2++) {
                float vv = __shfl_sync(0xFFFFFFFFu, v, i2);
                n = fmaf(vv, col[i2], n);
            }
            sc += msc;
            float m2 = n;
#pragma unroll
            for (int o = 16; o > 0; o >>= 1)
                m2 = fmaxf(m2, __shfl_xor_sync(0xFFFFFFFFu, m2, o));
            int ex = (__float_as_int(m2) >> 23) - 127;
            n *= __int_as_float((127 - ex) << 23);
            sc += (float)ex;
            v = n;
        }

        float x = v * __expf(end_trans[j]);
        if (lane >= LL) x = 0.0f;
#pragma unroll
        for (int o = 16; o > 0; o >>= 1)
            x += __shfl_xor_sync(0xFFFFFFFFu, x, o);
        if (lane == 0) sh_denom = (sc + __log2f(x)) * LN2;
    }
    else {  // numerator
        float part = 0.0f;
        int   cnt  = 0;
        for (int s0 = lane; s0 < SS; s0 += 32) {
            int   mk = mask[b * SS + s0];
            cnt += mk;
            int   lb = labels[b * SS + s0];
            float et = g_emis[((size_t)b * SS + s0) * LL + lb];
            if (s0 == 0) {
                part += start_trans[lb] + et;
            } else {
                int lp = labels[b * SS + s0 - 1];
                part += (trans[lp * LL + lb] + et) * (float)mk;
            }
        }
#pragma unroll
        for (int o = 16; o > 0; o >>= 1) {
            part += __shfl_down_sync(0xFFFFFFFFu, part, o);
            cnt  += __shfl_down_sync(0xFFFFFFFFu, cnt,  o);
        }
        if (lane == 0) {
            int li = cnt - 1; if (li < 0) li = 0;
            int lt = labels[b * SS + li];
            sh_num = part + end_trans[lt];
        }
    }

    __syncthreads();
    if (tid == 0) atomicAdd(out, sh_denom - sh_num);
}

// ---------------------------------------------------------------------------
extern "C" void kernel_launch(void* const* d_in, const int* in_sizes, int n_in,
                              void* d_out, int out_size)
{
    const float* hid    = (const float*)d_in[0];
    const int*   amask  = (const int*)  d_in[1];
    const int*   labels = (const int*)  d_in[2];
    const float* W      = (const float*)d_in[3];
    const float* bias   = (const float*)d_in[4];
    const float* st     = (const float*)d_in[5];
    const float* et     = (const float*)d_in[6];
    const float* tr     = (const float*)d_in[7];
    float* out = (float*)d_out;

    cudaFuncSetAttribute(fused_kernel,
        cudaFuncAttributeMaxDynamicSharedMemorySize, FUSED_SMEM);

    fused_kernel<<<NROWS / ROWS_PB, EB, FUSED_SMEM>>>(hid, W, bias, amask, tr, out);
    combine_kernel<<<BB, 64>>>(amask, labels, st, et, tr, out);
}

// round 11
// speedup vs baseline: 1.1812x; 1.1812x over previous
#include <cuda_runtime.h>
#include <cstdint>

#define BB 64
#define SS 512
#define HH 768
#define LL 9
#define NROWS (BB*SS)
#define NCH 16          // chunks per batch
#define CHL 32          // steps per chunk

static __device__ float g_mats[BB * NCH * 84];  // 9x9 linear matrices + scale
static __device__ float g_em0[BB * LL];         // emissions at t=0 per batch
static __device__ float g_nums[NROWS / 256];    // per-block numerator partials (128)
static __device__ int   g_cnts[NROWS / 256];    // per-block mask counts

#define LOG2E 1.4426950408889634f
#define LN2   0.6931471805599453f

// ---------------------------------------------------------------------------
// Fused kernel: emissions GEMM (register-prefetch pipelined) + numerator
// partial + per-chunk 9x9 transition products. 256 threads, 256 rows/block,
// 128 blocks. Block bx covers batch b = bx/2, timesteps [(bx&1)*256, +256),
// global chunks (bx&1)*8 + w for warps w = 0..7.
// ---------------------------------------------------------------------------
#define EB 256
#define ROWS_PB 256
#define HCH 32
#define NHC (HH / HCH)        // 24 chunks of h
#define XSTR 36               // floats per staged row (32 used + pad)
#define OFF_X 0
#define SM_XBUF (ROWS_PB * XSTR)          // 9216 floats
#define OFF_WC SM_XBUF                    // 9216
#define OFF_EM (OFF_WC + LL * HH)         // 16128
#define EMSTR 10
#define OFF_MK (OFF_EM + ROWS_PB * EMSTR) // 18688
#define OFF_TR (OFF_MK + ROWS_PB)         // 18944 : trans 81 floats
#define OFF_RF (OFF_TR + 81)              // 19025 : 8 warp partials (float)
#define OFF_RI (OFF_RF + 8)               // 19033 : 8 warp counts (int)
#define SM_FLOATS (OFF_RI + 8)            // 19041 floats
#define FUSED_SMEM (SM_FLOATS * 4)        // 76164 bytes

extern __shared__ float sm[];

__device__ __forceinline__ void rescale3(float& a0, float& a1, float& a2, float& sc)
{
    float mx = fmaxf(fmaxf(a0, a1), a2);
#pragma unroll
    for (int o = 16; o > 0; o >>= 1)
        mx = fmaxf(mx, __shfl_xor_sync(0xFFFFFFFFu, mx, o));
    int ex = (__float_as_int(mx) >> 23) - 127;
    float s = __int_as_float((127 - ex) << 23);
    a0 *= s; a1 *= s; a2 *= s;
    sc += (float)ex;
}

__global__ __launch_bounds__(EB) void fused_kernel(
    const float* __restrict__ hid,
    const float* __restrict__ W,
    const float* __restrict__ bias,
    const int*   __restrict__ mask,
    const int*   __restrict__ labels,
    const float* __restrict__ start_trans,
    const float* __restrict__ trans,
    float* __restrict__ out)
{
    const int tid  = threadIdx.x;
    const int bx   = blockIdx.x;
    const int r0   = bx * ROWS_PB;
    const int wid  = tid >> 5;
    const int lane = tid & 31;
    float* Xs = sm + OFF_X;           // [256][36]
    float* Wc = sm + OFF_WC;          // [9][768]
    float* Em = sm + OFF_EM;          // [256][10]
    int*   Mk = (int*)(sm + OFF_MK);  // [256]
    float* Tr = sm + OFF_TR;          // [81]
    float* RedF = sm + OFF_RF;        // [8]
    int*   RedI = (int*)(sm + OFF_RI);// [8]

    // each thread's 8 staging slots (row r, h4 group w4), fixed across chunks
    int s_r[8], s_w4[8];
#pragma unroll
    for (int o = 0; o < 8; o++) {
        int f = tid + o * EB;          // 0..2047
        s_r[o] = f >> 3; s_w4[o] = f & 7;
    }

    // ---- stage W (transposed to [j][h]), trans, mask; zero out scalar ----
    for (int idx = tid; idx < HH * LL; idx += EB) {
        int h = idx / LL, j = idx - h * LL;
        Wc[j * HH + h] = W[idx];
    }
    if (tid < LL * LL) Tr[tid] = trans[tid];
    Mk[tid] = mask[r0 + tid];   // row index == b*SS + t
    if (bx == 0 && tid == 0) out[0] = 0.0f;

    float acc[LL];
#pragma unroll
    for (int j = 0; j < LL; j++) acc[j] = bias[j];

    // ---- prologue: load chunk 0 into registers, store to smem ----
    float4 pf[8];
#pragma unroll
    for (int o = 0; o < 8; o++)
        pf[o] = *reinterpret_cast<const float4*>(
            hid + (size_t)(r0 + s_r[o]) * HH + 0 + 4 * s_w4[o]);
#pragma unroll
    for (int o = 0; o < 8; o++)
        *reinterpret_cast<float4*>(Xs + s_r[o] * XSTR + 4 * s_w4[o]) = pf[o];
    __syncthreads();   // chunk 0 staged (also covers Wc / Tr / Mk)

    for (int c = 0; c < NHC; c++) {
        // prefetch next chunk into registers (LDG latency hidden by compute)
        if (c + 1 < NHC) {
            const int hc = (c + 1) * HCH;
#pragma unroll
            for (int o = 0; o < 8; o++)
                pf[o] = *reinterpret_cast<const float4*>(
                    hid + (size_t)(r0 + s_r[o]) * HH + hc + 4 * s_w4[o]);
        }

        // compute on chunk c from smem
        const int hc = c * HCH;
        const float* xp = Xs + tid * XSTR;
#pragma unroll
        for (int h4 = 0; h4 < 8; h4++) {
            float4 x = *reinterpret_cast<const float4*>(xp + 4 * h4);
#pragma unroll
            for (int j = 0; j < LL; j++) {
                float4 w = *reinterpret_cast<const float4*>(Wc + j * HH + hc + 4 * h4);
                acc[j] = fmaf(x.x, w.x, fmaf(x.y, w.y,
                         fmaf(x.z, w.z, fmaf(x.w, w.w, acc[j]))));
            }
        }

        if (c + 1 < NHC) {
            __syncthreads();   // all done reading chunk c
#pragma unroll
            for (int o = 0; o < 8; o++)
                *reinterpret_cast<float4*>(Xs + s_r[o] * XSTR + 4 * s_w4[o]) = pf[o];
            __syncthreads();   // chunk c+1 staged
        }
    }

    // ---- store emissions to smem; t=0 row of each batch to global ----
    {
#pragma unroll
        for (int j = 0; j < LL; j++) Em[tid * EMSTR + j] = acc[j];
        if ((bx & 1) == 0 && tid == 0) {
#pragma unroll
            for (int j = 0; j < LL; j++) g_em0[(bx >> 1) * LL + j] = acc[j];
        }
    }
    __syncthreads();

    // ---- numerator partial: one step per thread, block-reduced ----
    {
        int   mkc = Mk[tid];
        int   gt  = r0 + tid;             // == b*SS + t
        int   ltb = labels[gt];
        float em  = Em[tid * EMSTR + ltb];
        float part;
        if ((gt & (SS - 1)) == 0) {       // t == 0
            part = start_trans[ltb] + em;
        } else {
            int lp = labels[gt - 1];
            part = (Tr[lp * LL + ltb] + em) * (float)mkc;
        }
#pragma unroll
        for (int o = 16; o > 0; o >>= 1) {
            part += __shfl_down_sync(0xFFFFFFFFu, part, o);
            mkc  += __shfl_down_sync(0xFFFFFFFFu, mkc,  o);
        }
        if (lane == 0) { RedF[wid] = part; RedI[wid] = mkc; }
    }
    __syncthreads();
    if (tid == 0) {
        float s = 0.0f; int c2 = 0;
#pragma unroll
        for (int w2 = 0; w2 < 8; w2++) { s += RedF[w2]; c2 += RedI[w2]; }
        g_nums[bx] = s; g_cnts[bx] = c2;
    }

    // ---- chunk phase: warp w computes chunk product for its 32 steps ----
    const int b  = bx >> 1;
    const int gc = (bx & 1) * 8 + wid;    // global chunk 0..15

    const int l  = (lane < 27) ? lane : 26;
    const int i  = l / 3;
    const int jb = 3 * (l - 3 * i);

    float ET0[LL], ET1[LL], ET2[LL];
#pragma unroll
    for (int k = 0; k < LL; k++) {
        ET0[k] = __expf(Tr[k * LL + jb + 0]);
        ET1[k] = __expf(Tr[k * LL + jb + 1]);
        ET2[k] = __expf(Tr[k * LL + jb + 2]);
    }

    float a0 = (i == jb + 0) ? 1.0f : 0.0f;
    float a1 = (i == jb + 1) ? 1.0f : 0.0f;
    float a2 = (i == jb + 2) ? 1.0f : 0.0f;
    float sc = 0.0f;

    const int lt0 = wid * CHL;                 // block-local step base
    const int ts  = (gc == 0) ? 1 : 0;         // skip t=0 globally

    float e0 = Em[(lt0 + ts) * EMSTR + jb];
    float e1 = Em[(lt0 + ts) * EMSTR + jb + 1];
    float e2 = Em[(lt0 + ts) * EMSTR + jb + 2];
    int mk = Mk[lt0 + ts];
    int cnt = 0;

    for (int t = ts; t < CHL; t++) {
        float f0 = __expf(e0), f1 = __expf(e1), f2 = __expf(e2);
        int m = mk;
        if (t + 1 < CHL) {
            e0 = Em[(lt0 + t + 1) * EMSTR + jb];
            e1 = Em[(lt0 + t + 1) * EMSTR + jb + 1];
            e2 = Em[(lt0 + t + 1) * EMSTR + jb + 2];
            mk = Mk[lt0 + t + 1];
        }
        float r0s = __shfl_sync(0xFFFFFFFFu, a0, 3*i    );
        float r1s = __shfl_sync(0xFFFFFFFFu, a1, 3*i    );
        float r2s = __shfl_sync(0xFFFFFFFFu, a2, 3*i    );
        float r3s = __shfl_sync(0xFFFFFFFFu, a0, 3*i + 1);
        float r4s = __shfl_sync(0xFFFFFFFFu, a1, 3*i + 1);
        float r5s = __shfl_sync(0xFFFFFFFFu, a2, 3*i + 1);
        float r6s = __shfl_sync(0xFFFFFFFFu, a0, 3*i + 2);
        float r7s = __shfl_sync(0xFFFFFFFFu, a1, 3*i + 2);
        float r8s = __shfl_sync(0xFFFFFFFFu, a2, 3*i + 2);

        float n0 = r0s*ET0[0] + r1s*ET0[1]; n0 += r2s*ET0[2] + r3s*ET0[3];
        n0 += r4s*ET0[4] + r5s*ET0[5];      n0 += r6s*ET0[6] + r7s*ET0[7] + r8s*ET0[8];
        float n1 = r0s*ET1[0] + r1s*ET1[1]; n1 += r2s*ET1[2] + r3s*ET1[3];
        n1 += r4s*ET1[4] + r5s*ET1[5];      n1 += r6s*ET1[6] + r7s*ET1[7] + r8s*ET1[8];
        float n2 = r0s*ET2[0] + r1s*ET2[1]; n2 += r2s*ET2[2] + r3s*ET2[3];
        n2 += r4s*ET2[4] + r5s*ET2[5];      n2 += r6s*ET2[6] + r7s*ET2[7] + r8s*ET2[8];
        n0 *= f0; n1 *= f1; n2 *= f2;

        a0 = m ? n0 : a0;  a1 = m ? n1 : a1;  a2 = m ? n2 : a2;
        if (((++cnt) & 7) == 0) rescale3(a0, a1, a2, sc);
    }

    rescale3(a0, a1, a2, sc);

    float* mb = g_mats + (size_t)(b * NCH + gc) * 84;
    if (lane < 27) {
        mb[i * LL + jb + 0] = a0;
        mb[i * LL + jb + 1] = a1;
        mb[i * LL + jb + 2] = a2;
    }
    if (lane == 0) mb[81] = sc;
}

// ---------------------------------------------------------------------------
// Kernel 2: per-batch fold (warp 0) + numerator finalize (warp 1).
// ---------------------------------------------------------------------------
__global__ __launch_bounds__(64) void combine_kernel(
    const int*   __restrict__ labels,
    const float* __restrict__ start_trans,
    const float* __restrict__ end_trans,
    float* __restrict__ out)
{
    __shared__ float Ms[NCH * 84];
    __shared__ float sh_denom, sh_num;
    const int b = blockIdx.x;
    const int tid = threadIdx.x;
    const int wid = tid >> 5;
    const int lane = tid & 31;

    // parallel coalesced staging of all 16 chunk matrices
    const float* gsrc = g_mats + (size_t)b * NCH * 84;
    for (int idx = tid; idx < NCH * 84; idx += 64) Ms[idx] = gsrc[idx];

    if (wid == 1 && lane == 0) {   // numerator finalize (overlaps staging)
        float num = g_nums[2 * b] + g_nums[2 * b + 1];
        int   cnt = g_cnts[2 * b] + g_cnts[2 * b + 1];
        int   li  = cnt - 1; if (li < 0) li = 0;
        sh_num = num + end_trans[labels[b * SS + li]];
    }
    __syncthreads();

    if (wid == 0) {
        const int j = (lane < LL) ? lane : (LL - 1);

        float a = start_trans[j] + g_em0[b * LL + j];
        float mx = a;
#pragma unroll
        for (int o = 16; o > 0; o >>= 1)
            mx = fmaxf(mx, __shfl_xor_sync(0xFFFFFFFFu, mx, o));
        float v  = __expf(a - mx);
        float sc = mx * LOG2E;

        for (int c = 0; c < NCH; c++) {
            const float* mb = Ms + c * 84;
            float col[LL];
#pragma unroll
            for (int i2 = 0; i2 < LL; i2++) col[i2] = mb[i2 * LL + j];
            float msc = mb[81];

            float n = 0.0f;
#pragma unroll
            for (int i2 = 0; i2 < LL; i2++) {
                float vv = __shfl_sync(0xFFFFFFFFu, v, i2);
                n = fmaf(vv, col[i2], n);
            }
            sc += msc;
            float m2 = n;
#pragma unroll
            for (int o = 16; o > 0; o >>= 1)
                m2 = fmaxf(m2, __shfl_xor_sync(0xFFFFFFFFu, m2, o));
            int ex = (__float_as_int(m2) >> 23) - 127;
            n *= __int_as_float((127 - ex) << 23);
            sc += (float)ex;
            v = n;
        }

        float x = v * __expf(end_trans[j]);
        if (lane >= LL) x = 0.0f;
#pragma unroll
        for (int o = 16; o > 0; o >>= 1)
            x += __shfl_xor_sync(0xFFFFFFFFu, x, o);
        if (lane == 0) {
            sh_denom = (sc + __log2f(x)) * LN2;
            atomicAdd(out, sh_denom - sh_num);
        }
    }
}

// ---------------------------------------------------------------------------
extern "C" void kernel_launch(void* const* d_in, const int* in_sizes, int n_in,
                              void* d_out, int out_size)
{
    const float* hid    = (const float*)d_in[0];
    const int*   amask  = (const int*)  d_in[1];
    const int*   labels = (const int*)  d_in[2];
    const float* W      = (const float*)d_in[3];
    const float* bias   = (const float*)d_in[4];
    const float* st     = (const float*)d_in[5];
    const float* et     = (const float*)d_in[6];
    const float* tr     = (const float*)d_in[7];
    float* out = (float*)d_out;

    cudaFuncSetAttribute(fused_kernel,
        cudaFuncAttributeMaxDynamicSharedMemorySize, FUSED_SMEM);

    fused_kernel<<<NROWS / ROWS_PB, EB, FUSED_SMEM>>>(
        hid, W, bias, amask, labels, st, tr, out);
    combine_kernel<<<BB, 64>>>(labels, st, et, out);
}

// round 12
// speedup vs baseline: 1.2845x; 1.0874x over previous
#include <cuda_runtime.h>
#include <cstdint>

#define BB 64
#define SS 512
#define HH 768
#define LL 9
#define NROWS (BB*SS)
#define NCH 16          // chunks per batch
#define CHL 32          // steps per chunk

static __device__ float g_mats[BB * NCH * 84];  // 9x9 linear matrices + scale
static __device__ float g_em0[BB * LL];         // emissions at t=0 per batch
static __device__ float g_nums[NROWS / 128];    // per-block numerator partials (256)
static __device__ int   g_cnts[NROWS / 128];    // per-block mask counts

#define LOG2E 1.4426950408889634f
#define LN2   0.6931471805599453f

// ---------------------------------------------------------------------------
// Fused kernel: emissions GEMM (register-prefetch pipelined) + numerator
// partial + per-chunk 9x9 transition products.
// 128 threads, 128 rows/block, 256 blocks (~2 blocks/SM resident).
// Block bx: batch b = bx/4, quarter q = bx&3, timesteps [q*128, +128),
// global chunks gc = q*4 + w for warps w = 0..3.
// ---------------------------------------------------------------------------
#define EB 128
#define ROWS_PB 128
#define HCH 32
#define NHC (HH / HCH)        // 24 chunks of h
#define XSTR 36               // floats per staged row (32 used + pad)
#define OFF_X 0
#define SM_XBUF (ROWS_PB * XSTR)          // 4608 floats
#define OFF_WC SM_XBUF                    // 4608
#define OFF_EM (OFF_WC + LL * HH)         // 11520
#define EMSTR 10
#define OFF_MK (OFF_EM + ROWS_PB * EMSTR) // 12800
#define OFF_TR (OFF_MK + ROWS_PB)         // 12928 : trans 81 floats
#define OFF_RF (OFF_TR + 81)              // 13009 : 4 warp partials (float)
#define OFF_RI (OFF_RF + 4)               // 13013 : 4 warp counts (int)
#define SM_FLOATS (OFF_RI + 4)            // 13017 floats
#define FUSED_SMEM (SM_FLOATS * 4)        // 52068 bytes

extern __shared__ float sm[];

__device__ __forceinline__ void rescale3(float& a0, float& a1, float& a2, float& sc)
{
    float mx = fmaxf(fmaxf(a0, a1), a2);
#pragma unroll
    for (int o = 16; o > 0; o >>= 1)
        mx = fmaxf(mx, __shfl_xor_sync(0xFFFFFFFFu, mx, o));
    int ex = (__float_as_int(mx) >> 23) - 127;
    float s = __int_as_float((127 - ex) << 23);
    a0 *= s; a1 *= s; a2 *= s;
    sc += (float)ex;
}

__global__ __launch_bounds__(EB) void fused_kernel(
    const float* __restrict__ hid,
    const float* __restrict__ W,
    const float* __restrict__ bias,
    const int*   __restrict__ mask,
    const int*   __restrict__ labels,
    const float* __restrict__ start_trans,
    const float* __restrict__ trans,
    float* __restrict__ out)
{
    const int tid  = threadIdx.x;
    const int bx   = blockIdx.x;
    const int r0   = bx * ROWS_PB;
    const int wid  = tid >> 5;
    const int lane = tid & 31;
    float* Xs = sm + OFF_X;           // [128][36]
    float* Wc = sm + OFF_WC;          // [9][768]
    float* Em = sm + OFF_EM;          // [128][10]
    int*   Mk = (int*)(sm + OFF_MK);  // [128]
    float* Tr = sm + OFF_TR;          // [81]
    float* RedF = sm + OFF_RF;        // [4]
    int*   RedI = (int*)(sm + OFF_RI);// [4]

    // each thread's 8 staging slots (row r, h4 group w4), fixed across chunks
    int s_r[8], s_w4[8];
#pragma unroll
    for (int o = 0; o < 8; o++) {
        int f = tid + o * EB;          // 0..1023
        s_r[o] = f >> 3; s_w4[o] = f & 7;
    }

    // ---- stage W (transposed to [j][h]), trans, mask; zero out scalar ----
    for (int idx = tid; idx < HH * LL; idx += EB) {
        int h = idx / LL, j = idx - h * LL;
        Wc[j * HH + h] = W[idx];
    }
    if (tid < LL * LL) Tr[tid] = trans[tid];
    Mk[tid] = mask[r0 + tid];   // row index == b*SS + t
    if (bx == 0 && tid == 0) out[0] = 0.0f;

    float acc[LL];
#pragma unroll
    for (int j = 0; j < LL; j++) acc[j] = bias[j];

    // ---- prologue: load chunk 0 into registers, store to smem ----
    float4 pf[8];
#pragma unroll
    for (int o = 0; o < 8; o++)
        pf[o] = *reinterpret_cast<const float4*>(
            hid + (size_t)(r0 + s_r[o]) * HH + 0 + 4 * s_w4[o]);
#pragma unroll
    for (int o = 0; o < 8; o++)
        *reinterpret_cast<float4*>(Xs + s_r[o] * XSTR + 4 * s_w4[o]) = pf[o];
    __syncthreads();   // chunk 0 staged (also covers Wc / Tr / Mk)

    for (int c = 0; c < NHC; c++) {
        // prefetch next chunk into registers (LDG latency hidden by compute)
        if (c + 1 < NHC) {
            const int hc = (c + 1) * HCH;
#pragma unroll
            for (int o = 0; o < 8; o++)
                pf[o] = *reinterpret_cast<const float4*>(
                    hid + (size_t)(r0 + s_r[o]) * HH + hc + 4 * s_w4[o]);
        }

        // compute on chunk c from smem
        const int hc = c * HCH;
        const float* xp = Xs + tid * XSTR;
#pragma unroll
        for (int h4 = 0; h4 < 8; h4++) {
            float4 x = *reinterpret_cast<const float4*>(xp + 4 * h4);
#pragma unroll
            for (int j = 0; j < LL; j++) {
                float4 w = *reinterpret_cast<const float4*>(Wc + j * HH + hc + 4 * h4);
                acc[j] = fmaf(x.x, w.x, fmaf(x.y, w.y,
                         fmaf(x.z, w.z, fmaf(x.w, w.w, acc[j]))));
            }
        }

        if (c + 1 < NHC) {
            __syncthreads();   // all done reading chunk c
#pragma unroll
            for (int o = 0; o < 8; o++)
                *reinterpret_cast<float4*>(Xs + s_r[o] * XSTR + 4 * s_w4[o]) = pf[o];
            __syncthreads();   // chunk c+1 staged
        }
    }

    // ---- store emissions to smem; t=0 row of each batch to global ----
    {
#pragma unroll
        for (int j = 0; j < LL; j++) Em[tid * EMSTR + j] = acc[j];
        if ((bx & 3) == 0 && tid == 0) {
#pragma unroll
            for (int j = 0; j < LL; j++) g_em0[(bx >> 2) * LL + j] = acc[j];
        }
    }
    __syncthreads();

    // ---- numerator partial: one step per thread, block-reduced ----
    {
        int   mkc = Mk[tid];
        int   gt  = r0 + tid;             // == b*SS + t
        int   ltb = labels[gt];
        float em  = Em[tid * EMSTR + ltb];
        float part;
        if ((gt & (SS - 1)) == 0) {       // t == 0
            part = start_trans[ltb] + em;
        } else {
            int lp = labels[gt - 1];
            part = (Tr[lp * LL + ltb] + em) * (float)mkc;
        }
#pragma unroll
        for (int o = 16; o > 0; o >>= 1) {
            part += __shfl_down_sync(0xFFFFFFFFu, part, o);
            mkc  += __shfl_down_sync(0xFFFFFFFFu, mkc,  o);
        }
        if (lane == 0) { RedF[wid] = part; RedI[wid] = mkc; }
    }
    __syncthreads();
    if (tid == 0) {
        float s = 0.0f; int c2 = 0;
#pragma unroll
        for (int w2 = 0; w2 < 4; w2++) { s += RedF[w2]; c2 += RedI[w2]; }
        g_nums[bx] = s; g_cnts[bx] = c2;
    }

    // ---- chunk phase: warp w computes chunk product for its 32 steps ----
    const int b  = bx >> 2;
    const int gc = (bx & 3) * 4 + wid;    // global chunk 0..15

    const int l  = (lane < 27) ? lane : 26;
    const int i  = l / 3;
    const int jb = 3 * (l - 3 * i);

    float ET0[LL], ET1[LL], ET2[LL];
#pragma unroll
    for (int k = 0; k < LL; k++) {
        ET0[k] = __expf(Tr[k * LL + jb + 0]);
        ET1[k] = __expf(Tr[k * LL + jb + 1]);
        ET2[k] = __expf(Tr[k * LL + jb + 2]);
    }

    float a0 = (i == jb + 0) ? 1.0f : 0.0f;
    float a1 = (i == jb + 1) ? 1.0f : 0.0f;
    float a2 = (i == jb + 2) ? 1.0f : 0.0f;
    float sc = 0.0f;

    const int lt0 = wid * CHL;                 // block-local step base
    const int ts  = (gc == 0) ? 1 : 0;         // skip t=0 globally

    float e0 = Em[(lt0 + ts) * EMSTR + jb];
    float e1 = Em[(lt0 + ts) * EMSTR + jb + 1];
    float e2 = Em[(lt0 + ts) * EMSTR + jb + 2];
    int mk = Mk[lt0 + ts];
    int cnt = 0;

    for (int t = ts; t < CHL; t++) {
        float f0 = __expf(e0), f1 = __expf(e1), f2 = __expf(e2);
        int m = mk;
        if (t + 1 < CHL) {
            e0 = Em[(lt0 + t + 1) * EMSTR + jb];
            e1 = Em[(lt0 + t + 1) * EMSTR + jb + 1];
            e2 = Em[(lt0 + t + 1) * EMSTR + jb + 2];
            mk = Mk[lt0 + t + 1];
        }
        float r0s = __shfl_sync(0xFFFFFFFFu, a0, 3*i    );
        float r1s = __shfl_sync(0xFFFFFFFFu, a1, 3*i    );
        float r2s = __shfl_sync(0xFFFFFFFFu, a2, 3*i    );
        float r3s = __shfl_sync(0xFFFFFFFFu, a0, 3*i + 1);
        float r4s = __shfl_sync(0xFFFFFFFFu, a1, 3*i + 1);
        float r5s = __shfl_sync(0xFFFFFFFFu, a2, 3*i + 1);
        float r6s = __shfl_sync(0xFFFFFFFFu, a0, 3*i + 2);
        float r7s = __shfl_sync(0xFFFFFFFFu, a1, 3*i + 2);
        float r8s = __shfl_sync(0xFFFFFFFFu, a2, 3*i + 2);

        float n0 = r0s*ET0[0] + r1s*ET0[1]; n0 += r2s*ET0[2] + r3s*ET0[3];
        n0 += r4s*ET0[4] + r5s*ET0[5];      n0 += r6s*ET0[6] + r7s*ET0[7] + r8s*ET0[8];
        float n1 = r0s*ET1[0] + r1s*ET1[1]; n1 += r2s*ET1[2] + r3s*ET1[3];
        n1 += r4s*ET1[4] + r5s*ET1[5];      n1 += r6s*ET1[6] + r7s*ET1[7] + r8s*ET1[8];
        float n2 = r0s*ET2[0] + r1s*ET2[1]; n2 += r2s*ET2[2] + r3s*ET2[3];
        n2 += r4s*ET2[4] + r5s*ET2[5];      n2 += r6s*ET2[6] + r7s*ET2[7] + r8s*ET2[8];
        n0 *= f0; n1 *= f1; n2 *= f2;

        a0 = m ? n0 : a0;  a1 = m ? n1 : a1;  a2 = m ? n2 : a2;
        if (((++cnt) & 7) == 0) rescale3(a0, a1, a2, sc);
    }

    rescale3(a0, a1, a2, sc);

    float* mb = g_mats + (size_t)(b * NCH + gc) * 84;
    if (lane < 27) {
        mb[i * LL + jb + 0] = a0;
        mb[i * LL + jb + 1] = a1;
        mb[i * LL + jb + 2] = a2;
    }
    if (lane == 0) mb[81] = sc;
}

// ---------------------------------------------------------------------------
// Kernel 2: per-batch fold (warp 0) + numerator finalize (warp 1).
// ---------------------------------------------------------------------------
__global__ __launch_bounds__(64) void combine_kernel(
    const int*   __restrict__ labels,
    const float* __restrict__ start_trans,
    const float* __restrict__ end_trans,
    float* __restrict__ out)
{
    __shared__ float Ms[NCH * 84];
    __shared__ float sh_denom, sh_num;
    const int b = blockIdx.x;
    const int tid = threadIdx.x;
    const int wid = tid >> 5;
    const int lane = tid & 31;

    // parallel coalesced staging of all 16 chunk matrices
    const float* gsrc = g_mats + (size_t)b * NCH * 84;
    for (int idx = tid; idx < NCH * 84; idx += 64) Ms[idx] = gsrc[idx];

    if (wid == 1 && lane == 0) {   // numerator finalize (overlaps staging)
        float num = g_nums[4*b] + g_nums[4*b + 1] + g_nums[4*b + 2] + g_nums[4*b + 3];
        int   cnt = g_cnts[4*b] + g_cnts[4*b + 1] + g_cnts[4*b + 2] + g_cnts[4*b + 3];
        int   li  = cnt - 1; if (li < 0) li = 0;
        sh_num = num + end_trans[labels[b * SS + li]];
    }
    __syncthreads();

    if (wid == 0) {
        const int j = (lane < LL) ? lane : (LL - 1);

        float a = start_trans[j] + g_em0[b * LL + j];
        float mx = a;
#pragma unroll
        for (int o = 16; o > 0; o >>= 1)
            mx = fmaxf(mx, __shfl_xor_sync(0xFFFFFFFFu, mx, o));
        float v  = __expf(a - mx);
        float sc = mx * LOG2E;

        for (int c = 0; c < NCH; c++) {
            const float* mb = Ms + c * 84;
            float col[LL];
#pragma unroll
            for (int i2 = 0; i2 < LL; i2++) col[i2] = mb[i2 * LL + j];
            float msc = mb[81];

            float n = 0.0f;
#pragma unroll
            for (int i2 = 0; i2 < LL; i2++) {
                float vv = __shfl_sync(0xFFFFFFFFu, v, i2);
                n = fmaf(vv, col[i2], n);
            }
            sc += msc;
            float m2 = n;
#pragma unroll
            for (int o = 16; o > 0; o >>= 1)
                m2 = fmaxf(m2, __shfl_xor_sync(0xFFFFFFFFu, m2, o));
            int ex = (__float_as_int(m2) >> 23) - 127;
            n *= __int_as_float((127 - ex) << 23);
            sc += (float)ex;
            v = n;
        }

        float x = v * __expf(end_trans[j]);
        if (lane >= LL) x = 0.0f;
#pragma unroll
        for (int o = 16; o > 0; o >>= 1)
            x += __shfl_xor_sync(0xFFFFFFFFu, x, o);
        if (lane == 0) {
            sh_denom = (sc + __log2f(x)) * LN2;
            atomicAdd(out, sh_denom - sh_num);
        }
    }
}

// ---------------------------------------------------------------------------
extern "C" void kernel_launch(void* const* d_in, const int* in_sizes, int n_in,
                              void* d_out, int out_size)
{
    const float* hid    = (const float*)d_in[0];
    const int*   amask  = (const int*)  d_in[1];
    const int*   labels = (const int*)  d_in[2];
    const float* W      = (const float*)d_in[3];
    const float* bias   = (const float*)d_in[4];
    const float* st     = (const float*)d_in[5];
    const float* et     = (const float*)d_in[6];
    const float* tr     = (const float*)d_in[7];
    float* out = (float*)d_out;

    cudaFuncSetAttribute(fused_kernel,
        cudaFuncAttributeMaxDynamicSharedMemorySize, FUSED_SMEM);

    fused_kernel<<<NROWS / ROWS_PB, EB, FUSED_SMEM>>>(
        hid, W, bias, amask, labels, st, tr, out);
    combine_kernel<<<BB, 64>>>(labels, st, et, out);
}

// round 13
// speedup vs baseline: 1.3191x; 1.0269x over previous
#include <cuda_runtime.h>
#include <cstdint>

#define BB 64
#define SS 512
#define HH 768
#define LL 9
#define NROWS (BB*SS)
#define NCH 16          // chunks per batch
#define CHL 32          // steps per chunk

static __device__ float g_mats[BB * NCH * 84];  // 9x9 linear matrices + scale
static __device__ float g_em0[BB * LL];         // emissions at t=0 per batch
static __device__ float g_nums[NROWS / 128];    // per-block numerator partials (256)
static __device__ int   g_cnts[NROWS / 128];    // per-block mask counts

#define LOG2E 1.4426950408889634f
#define LN2   0.6931471805599453f

// ---------------------------------------------------------------------------
// Fused kernel: emissions GEMM (f32x2 packed FMA, double-buffered smem,
// register-prefetch) + numerator partial + per-chunk 9x9 transition products.
// 128 threads, 128 rows/block, 256 blocks.
// Block bx: batch b = bx/4, quarter q = bx&3, timesteps [q*128, +128),
// global chunks gc = q*4 + w for warps w = 0..3.
// ---------------------------------------------------------------------------
#define EB 128
#define ROWS_PB 128
#define HCH 32
#define NHC (HH / HCH)        // 24 chunks of h
#define XSTR 36               // floats per staged row (32 used + pad, 16B-aligned)
#define OFF_X0 0
#define OFF_X1 (ROWS_PB * XSTR)           // 4608
#define OFF_WC (2 * ROWS_PB * XSTR)       // 9216
#define OFF_EM (OFF_WC + LL * HH)         // 16128
#define EMSTR 10
#define OFF_MK (OFF_EM + ROWS_PB * EMSTR) // 17408
#define OFF_TR (OFF_MK + ROWS_PB)         // 17536 : trans 81 floats
#define OFF_RF (OFF_TR + 81)              // 17617 : 4 warp partials (float)
#define OFF_RI (OFF_RF + 4)               // 17621 : 4 warp counts (int)
#define SM_FLOATS (OFF_RI + 4)            // 17625 floats
#define FUSED_SMEM (SM_FLOATS * 4)        // 70500 bytes

extern __shared__ float sm[];

// packed dual-FMA: d.lo += a.lo*b.lo ; d.hi += a.hi*b.hi
__device__ __forceinline__ void fma2(unsigned long long& d,
                                     unsigned long long a,
                                     unsigned long long b) {
    asm("fma.rn.f32x2 %0, %1, %2, %0;" : "+l"(d) : "l"(a), "l"(b));
}

__device__ __forceinline__ void rescale3(float& a0, float& a1, float& a2, float& sc)
{
    float mx = fmaxf(fmaxf(a0, a1), a2);
#pragma unroll
    for (int o = 16; o > 0; o >>= 1)
        mx = fmaxf(mx, __shfl_xor_sync(0xFFFFFFFFu, mx, o));
    int ex = (__float_as_int(mx) >> 23) - 127;
    float s = __int_as_float((127 - ex) << 23);
    a0 *= s; a1 *= s; a2 *= s;
    sc += (float)ex;
}

__global__ __launch_bounds__(EB) void fused_kernel(
    const float* __restrict__ hid,
    const float* __restrict__ W,
    const float* __restrict__ bias,
    const int*   __restrict__ mask,
    const int*   __restrict__ labels,
    const float* __restrict__ start_trans,
    const float* __restrict__ trans,
    float* __restrict__ out)
{
    const int tid  = threadIdx.x;
    const int bx   = blockIdx.x;
    const int r0   = bx * ROWS_PB;
    const int wid  = tid >> 5;
    const int lane = tid & 31;
    float* Wc = sm + OFF_WC;          // [9][768]
    float* Em = sm + OFF_EM;          // [128][10]
    int*   Mk = (int*)(sm + OFF_MK);  // [128]
    float* Tr = sm + OFF_TR;          // [81]
    float* RedF = sm + OFF_RF;        // [4]
    int*   RedI = (int*)(sm + OFF_RI);// [4]

    // each thread's 8 staging slots (row r, h4 group w4), fixed across chunks
    int s_r[8], s_w4[8];
#pragma unroll
    for (int o = 0; o < 8; o++) {
        int f = tid + o * EB;          // 0..1023
        s_r[o] = f >> 3; s_w4[o] = f & 7;
    }

    // ---- stage W (transposed to [j][h]), trans, mask; zero out scalar ----
    for (int idx = tid; idx < HH * LL; idx += EB) {
        int h = idx / LL, j = idx - h * LL;
        Wc[j * HH + h] = W[idx];
    }
    if (tid < LL * LL) Tr[tid] = trans[tid];
    Mk[tid] = mask[r0 + tid];   // row index == b*SS + t
    if (bx == 0 && tid == 0) out[0] = 0.0f;

    unsigned long long accp[LL];      // packed (even-h, odd-h) accumulators
#pragma unroll
    for (int j = 0; j < LL; j++) accp[j] = 0ull;

    // ---- prologue: load chunk 0 into registers, store to buffer 0 ----
    float4 pf[8];
#pragma unroll
    for (int o = 0; o < 8; o++)
        pf[o] = *reinterpret_cast<const float4*>(
            hid + (size_t)(r0 + s_r[o]) * HH + 0 + 4 * s_w4[o]);
#pragma unroll
    for (int o = 0; o < 8; o++)
        *reinterpret_cast<float4*>(sm + OFF_X0 + s_r[o] * XSTR + 4 * s_w4[o]) = pf[o];
    __syncthreads();   // chunk 0 staged (also covers Wc / Tr / Mk)

    for (int c = 0; c < NHC; c++) {
        // prefetch next chunk into registers (LDG latency hidden by compute)
        if (c + 1 < NHC) {
            const int hc = (c + 1) * HCH;
#pragma unroll
            for (int o = 0; o < 8; o++)
                pf[o] = *reinterpret_cast<const float4*>(
                    hid + (size_t)(r0 + s_r[o]) * HH + hc + 4 * s_w4[o]);
        }

        // compute on chunk c from current buffer (packed f32x2 FMA)
        const int bufo = (c & 1) ? OFF_X1 : OFF_X0;
        const int hc = c * HCH;
        const float* xp = sm + bufo + tid * XSTR;
#pragma unroll
        for (int h4 = 0; h4 < 8; h4++) {
            ulonglong2 xv = *reinterpret_cast<const ulonglong2*>(xp + 4 * h4);
#pragma unroll
            for (int j = 0; j < LL; j++) {
                ulonglong2 wv = *reinterpret_cast<const ulonglong2*>(
                    Wc + j * HH + hc + 4 * h4);
                fma2(accp[j], xv.x, wv.x);
                fma2(accp[j], xv.y, wv.y);
            }
        }

        if (c + 1 < NHC) {
            // store next chunk into the OTHER buffer (no one reads it yet),
            // then one barrier gates entry to the next compute.
            const int nbo = (c & 1) ? OFF_X0 : OFF_X1;
#pragma unroll
            for (int o = 0; o < 8; o++)
                *reinterpret_cast<float4*>(sm + nbo + s_r[o] * XSTR + 4 * s_w4[o]) = pf[o];
            __syncthreads();
        }
    }

    // ---- unpack accumulators, add bias ----
    float acc[LL];
#pragma unroll
    for (int j = 0; j < LL; j++) {
        float lo = __int_as_float((int)(accp[j] & 0xffffffffull));
        float hi = __int_as_float((int)(accp[j] >> 32));
        acc[j] = lo + hi + bias[j];
    }

    // ---- store emissions to smem; t=0 row of each batch to global ----
    {
#pragma unroll
        for (int j = 0; j < LL; j++) Em[tid * EMSTR + j] = acc[j];
        if ((bx & 3) == 0 && tid == 0) {
#pragma unroll
            for (int j = 0; j < LL; j++) g_em0[(bx >> 2) * LL + j] = acc[j];
        }
    }
    __syncthreads();

    // ---- numerator partial: one step per thread, block-reduced ----
    {
        int   mkc = Mk[tid];
        int   gt  = r0 + tid;             // == b*SS + t
        int   ltb = labels[gt];
        float em  = Em[tid * EMSTR + ltb];
        float part;
        if ((gt & (SS - 1)) == 0) {       // t == 0
            part = start_trans[ltb] + em;
        } else {
            int lp = labels[gt - 1];
            part = (Tr[lp * LL + ltb] + em) * (float)mkc;
        }
#pragma unroll
        for (int o = 16; o > 0; o >>= 1) {
            part += __shfl_down_sync(0xFFFFFFFFu, part, o);
            mkc  += __shfl_down_sync(0xFFFFFFFFu, mkc,  o);
        }
        if (lane == 0) { RedF[wid] = part; RedI[wid] = mkc; }
    }
    __syncthreads();
    if (tid == 0) {
        float s = 0.0f; int c2 = 0;
#pragma unroll
        for (int w2 = 0; w2 < 4; w2++) { s += RedF[w2]; c2 += RedI[w2]; }
        g_nums[bx] = s; g_cnts[bx] = c2;
    }

    // ---- chunk phase: warp w computes chunk product for its 32 steps ----
    const int b  = bx >> 2;
    const int gc = (bx & 3) * 4 + wid;    // global chunk 0..15

    const int l  = (lane < 27) ? lane : 26;
    const int i  = l / 3;
    const int jb = 3 * (l - 3 * i);

    float ET0[LL], ET1[LL], ET2[LL];
#pragma unroll
    for (int k = 0; k < LL; k++) {
        ET0[k] = __expf(Tr[k * LL + jb + 0]);
        ET1[k] = __expf(Tr[k * LL + jb + 1]);
        ET2[k] = __expf(Tr[k * LL + jb + 2]);
    }

    float a0 = (i == jb + 0) ? 1.0f : 0.0f;
    float a1 = (i == jb + 1) ? 1.0f : 0.0f;
    float a2 = (i == jb + 2) ? 1.0f : 0.0f;
    float sc = 0.0f;

    const int lt0 = wid * CHL;                 // block-local step base
    const int ts  = (gc == 0) ? 1 : 0;         // skip t=0 globally

    float e0 = Em[(lt0 + ts) * EMSTR + jb];
    float e1 = Em[(lt0 + ts) * EMSTR + jb + 1];
    float e2 = Em[(lt0 + ts) * EMSTR + jb + 2];
    int mk = Mk[lt0 + ts];
    int cnt = 0;

    for (int t = ts; t < CHL; t++) {
        float f0 = __expf(e0), f1 = __expf(e1), f2 = __expf(e2);
        int m = mk;
        if (t + 1 < CHL) {
            e0 = Em[(lt0 + t + 1) * EMSTR + jb];
            e1 = Em[(lt0 + t + 1) * EMSTR + jb + 1];
            e2 = Em[(lt0 + t + 1) * EMSTR + jb + 2];
            mk = Mk[lt0 + t + 1];
        }
        float r0s = __shfl_sync(0xFFFFFFFFu, a0, 3*i    );
        float r1s = __shfl_sync(0xFFFFFFFFu, a1, 3*i    );
        float r2s = __shfl_sync(0xFFFFFFFFu, a2, 3*i    );
        float r3s = __shfl_sync(0xFFFFFFFFu, a0, 3*i + 1);
        float r4s = __shfl_sync(0xFFFFFFFFu, a1, 3*i + 1);
        float r5s = __shfl_sync(0xFFFFFFFFu, a2, 3*i + 1);
        float r6s = __shfl_sync(0xFFFFFFFFu, a0, 3*i + 2);
        float r7s = __shfl_sync(0xFFFFFFFFu, a1, 3*i + 2);
        float r8s = __shfl_sync(0xFFFFFFFFu, a2, 3*i + 2);

        float n0 = r0s*ET0[0] + r1s*ET0[1]; n0 += r2s*ET0[2] + r3s*ET0[3];
        n0 += r4s*ET0[4] + r5s*ET0[5];      n0 += r6s*ET0[6] + r7s*ET0[7] + r8s*ET0[8];
        float n1 = r0s*ET1[0] + r1s*ET1[1]; n1 += r2s*ET1[2] + r3s*ET1[3];
        n1 += r4s*ET1[4] + r5s*ET1[5];      n1 += r6s*ET1[6] + r7s*ET1[7] + r8s*ET1[8];
        float n2 = r0s*ET2[0] + r1s*ET2[1]; n2 += r2s*ET2[2] + r3s*ET2[3];
        n2 += r4s*ET2[4] + r5s*ET2[5];      n2 += r6s*ET2[6] + r7s*ET2[7] + r8s*ET2[8];
        n0 *= f0; n1 *= f1; n2 *= f2;

        a0 = m ? n0 : a0;  a1 = m ? n1 : a1;  a2 = m ? n2 : a2;
        if (((++cnt) & 7) == 0) rescale3(a0, a1, a2, sc);
    }

    rescale3(a0, a1, a2, sc);

    float* mb = g_mats + (size_t)(b * NCH + gc) * 84;
    if (lane < 27) {
        mb[i * LL + jb + 0] = a0;
        mb[i * LL + jb + 1] = a1;
        mb[i * LL + jb + 2] = a2;
    }
    if (lane == 0) mb[81] = sc;
}

// ---------------------------------------------------------------------------
// Kernel 2: per-batch fold (warp 0) + numerator finalize (warp 1).
// ---------------------------------------------------------------------------
__global__ __launch_bounds__(64) void combine_kernel(
    const int*   __restrict__ labels,
    const float* __restrict__ start_trans,
    const float* __restrict__ end_trans,
    float* __restrict__ out)
{
    __shared__ float Ms[NCH * 84];
    __shared__ float sh_denom, sh_num;
    const int b = blockIdx.x;
    const int tid = threadIdx.x;
    const int wid = tid >> 5;
    const int lane = tid & 31;

    // parallel coalesced staging of all 16 chunk matrices
    const float* gsrc = g_mats + (size_t)b * NCH * 84;
    for (int idx = tid; idx < NCH * 84; idx += 64) Ms[idx] = gsrc[idx];

    if (wid == 1 && lane == 0) {   // numerator finalize (overlaps staging)
        float num = g_nums[4*b] + g_nums[4*b + 1] + g_nums[4*b + 2] + g_nums[4*b + 3];
        int   cnt = g_cnts[4*b] + g_cnts[4*b + 1] + g_cnts[4*b + 2] + g_cnts[4*b + 3];
        int   li  = cnt - 1; if (li < 0) li = 0;
        sh_num = num + end_trans[labels[b * SS + li]];
    }
    __syncthreads();

    if (wid == 0) {
        const int j = (lane < LL) ? lane : (LL - 1);

        float a = start_trans[j] + g_em0[b * LL + j];
        float mx = a;
#pragma unroll
        for (int o = 16; o > 0; o >>= 1)
            mx = fmaxf(mx, __shfl_xor_sync(0xFFFFFFFFu, mx, o));
        float v  = __expf(a - mx);
        float sc = mx * LOG2E;

        for (int c = 0; c < NCH; c++) {
            const float* mb = Ms + c * 84;
            float col[LL];
#pragma unroll
            for (int i2 = 0; i2 < LL; i2++) col[i2] = mb[i2 * LL + j];
            float msc = mb[81];

            float n = 0.0f;
#pragma unroll
            for (int i2 = 0; i2 < LL; i2++) {
                float vv = __shfl_sync(0xFFFFFFFFu, v, i2);
                n = fmaf(vv, col[i2], n);
            }
            sc += msc;
            float m2 = n;
#pragma unroll
            for (int o = 16; o > 0; o >>= 1)
                m2 = fmaxf(m2, __shfl_xor_sync(0xFFFFFFFFu, m2, o));
            int ex = (__float_as_int(m2) >> 23) - 127;
            n *= __int_as_float((127 - ex) << 23);
            sc += (float)ex;
            v = n;
        }

        float x = v * __expf(end_trans[j]);
        if (lane >= LL) x = 0.0f;
#pragma unroll
        for (int o = 16; o > 0; o >>= 1)
            x += __shfl_xor_sync(0xFFFFFFFFu, x, o);
        if (lane == 0) {
            sh_denom = (sc + __log2f(x)) * LN2;
            atomicAdd(out, sh_denom - sh_num);
        }
    }
}

// ---------------------------------------------------------------------------
extern "C" void kernel_launch(void* const* d_in, const int* in_sizes, int n_in,
                              void* d_out, int out_size)
{
    const float* hid    = (const float*)d_in[0];
    const int*   amask  = (const int*)  d_in[1];
    const int*   labels = (const int*)  d_in[2];
    const float* W      = (const float*)d_in[3];
    const float* bias   = (const float*)d_in[4];
    const float* st     = (const float*)d_in[5];
    const float* et     = (const float*)d_in[6];
    const float* tr     = (const float*)d_in[7];
    float* out = (float*)d_out;

    cudaFuncSetAttribute(fused_kernel,
        cudaFuncAttributeMaxDynamicSharedMemorySize, FUSED_SMEM);

    fused_kernel<<<NROWS / ROWS_PB, EB, FUSED_SMEM>>>(
        hid, W, bias, amask, labels, st, tr, out);
    combine_kernel<<<BB, 64>>>(labels, st, et, out);
}